// round 2
// baseline (speedup 1.0000x reference)
#include <cuda_runtime.h>
#include <cuda_bf16.h>

// Inputs (metadata order):
// 0: pred         float32 [2,000,000]
// 1: constr_idx   int32   [20,000,000]
// 2: var_idx      int32   [20,000,000]
// 3: coeff        float32 [20,000,000]
// 4: constr_rhs   float32 [1,000,000]
// 5: constr_sense int32   [1,000,000]
// 6: n_vars       (scalar)
// 7: n_constrs    (scalar)
// Output: scalar float (mean violation)

#define MAX_VARS    2000000
#define MAX_CONSTRS 1000000

__device__ float g_values[MAX_VARS];   // sigmoid(pred)
__device__ float g_ax[MAX_CONSTRS];    // accumulated A@x

// ---------------------------------------------------------------------------
// Kernel 1: values = sigmoid(pred), vectorized float4
// ---------------------------------------------------------------------------
__global__ void sigmoid_kernel(const float* __restrict__ pred, int n4) {
    int i = blockIdx.x * blockDim.x + threadIdx.x;
    if (i < n4) {
        float4 x = reinterpret_cast<const float4*>(pred)[i];
        float4 y;
        y.x = __frcp_rn(1.0f + __expf(-x.x));
        y.y = __frcp_rn(1.0f + __expf(-x.y));
        y.z = __frcp_rn(1.0f + __expf(-x.z));
        y.w = __frcp_rn(1.0f + __expf(-x.w));
        reinterpret_cast<float4*>(g_values)[i] = y;
    }
}

// ---------------------------------------------------------------------------
// Kernel 2: zero ax and the output scalar
// ---------------------------------------------------------------------------
__global__ void zero_kernel(float* __restrict__ out, int n4) {
    int i = blockIdx.x * blockDim.x + threadIdx.x;
    if (i < n4) {
        reinterpret_cast<float4*>(g_ax)[i] = make_float4(0.f, 0.f, 0.f, 0.f);
    }
    if (i == 0) *out = 0.0f;
}

// ---------------------------------------------------------------------------
// Kernel 3: scatter-add  ax[cidx[k]] += coeff[k] * values[vidx[k]]
// 4 nonzeros per thread, vectorized loads for MLP.
// ---------------------------------------------------------------------------
__global__ void scatter_kernel(const int* __restrict__ cidx,
                               const int* __restrict__ vidx,
                               const float* __restrict__ coeff,
                               int nnz4) {
    int i = blockIdx.x * blockDim.x + threadIdx.x;
    if (i < nnz4) {
        int4   c = reinterpret_cast<const int4*>(cidx)[i];
        int4   v = reinterpret_cast<const int4*>(vidx)[i];
        float4 a = reinterpret_cast<const float4*>(coeff)[i];
        // Gather (L2-resident values array), then fire 4 no-return atomics (REDG)
        float p0 = a.x * __ldg(&g_values[v.x]);
        float p1 = a.y * __ldg(&g_values[v.y]);
        float p2 = a.z * __ldg(&g_values[v.z]);
        float p3 = a.w * __ldg(&g_values[v.w]);
        atomicAdd(&g_ax[c.x], p0);
        atomicAdd(&g_ax[c.y], p1);
        atomicAdd(&g_ax[c.z], p2);
        atomicAdd(&g_ax[c.w], p3);
    }
}

// ---------------------------------------------------------------------------
// Kernel 4: violations + mean reduction
// ---------------------------------------------------------------------------
__global__ void reduce_kernel(const float* __restrict__ rhs,
                              const int* __restrict__ sense,
                              float* __restrict__ out,
                              int n, float inv_n) {
    float s = 0.0f;
    int stride = gridDim.x * blockDim.x;
    for (int i = blockIdx.x * blockDim.x + threadIdx.x; i < n; i += stride) {
        float diff = g_ax[i] - rhs[i];
        int sn = sense[i];
        float v;
        if (sn == 1)      v = fmaxf(diff, 0.0f);
        else if (sn == 2) v = fmaxf(-diff, 0.0f);
        else if (sn == 3) v = fabsf(diff);
        else              v = 0.0f;
        s += v;
    }
    // warp reduce
    #pragma unroll
    for (int off = 16; off > 0; off >>= 1)
        s += __shfl_down_sync(0xFFFFFFFFu, s, off);

    __shared__ float warp_sums[32];
    int lane = threadIdx.x & 31;
    int wid  = threadIdx.x >> 5;
    if (lane == 0) warp_sums[wid] = s;
    __syncthreads();
    int nwarps = blockDim.x >> 5;
    if (wid == 0) {
        float t = (lane < nwarps) ? warp_sums[lane] : 0.0f;
        #pragma unroll
        for (int off = 16; off > 0; off >>= 1)
            t += __shfl_down_sync(0xFFFFFFFFu, t, off);
        if (lane == 0) atomicAdd(out, t * inv_n);
    }
}

// ---------------------------------------------------------------------------
extern "C" void kernel_launch(void* const* d_in, const int* in_sizes, int n_in,
                              void* d_out, int out_size) {
    const float* pred   = (const float*)d_in[0];
    const int*   cidx   = (const int*)  d_in[1];
    const int*   vidx   = (const int*)  d_in[2];
    const float* coeff  = (const float*)d_in[3];
    const float* rhs    = (const float*)d_in[4];
    const int*   sense  = (const int*)  d_in[5];

    int n_vars    = in_sizes[0];
    int nnz       = in_sizes[1];
    int n_constrs = in_sizes[4];

    float* out = (float*)d_out;

    // 1) sigmoid
    {
        int n4 = n_vars / 4;
        int threads = 256;
        int blocks = (n4 + threads - 1) / threads;
        sigmoid_kernel<<<blocks, threads>>>(pred, n4);
        // tail (n_vars not divisible by 4) — handled only if needed
    }

    // 2) zero ax + out
    {
        int n4 = (n_constrs + 3) / 4;   // MAX_CONSTRS is 4-divisible; rounding safe
        int threads = 256;
        int blocks = (n4 + threads - 1) / threads;
        zero_kernel<<<blocks, threads>>>(out, n4);
    }

    // 3) scatter
    {
        int nnz4 = nnz / 4;
        int threads = 256;
        int blocks = (nnz4 + threads - 1) / threads;
        scatter_kernel<<<blocks, threads>>>(cidx, vidx, coeff, nnz4);
    }

    // 4) violations + mean
    {
        int threads = 256;
        int blocks = 1184;   // 8 per SM
        reduce_kernel<<<blocks, threads>>>(rhs, sense, out, n_constrs,
                                           1.0f / (float)n_constrs);
    }
}